// round 1
// baseline (speedup 1.0000x reference)
#include <cuda_runtime.h>
#include <math.h>

#define N_NODES 8192
#define N_EDGES 32768
#define FN 32
#define FE 16
#define H 73
#define HH (H*H)          // 5329
#define NB 64             // batches
#define T_MP 3
#define T_S2S 12

// ---------------- device scratch (static globals; no cudaMalloc allowed) ----------
__device__ float g_h[N_NODES * H];
__device__ float g_RH[N_EDGES * H];
__device__ float g_agg[N_NODES * H];
__device__ float g_A[(size_t)N_EDGES * HH];   // 698 MB edge-network matrices

__device__ __forceinline__ float sigf(float x) { return 1.0f / (1.0f + expf(-x)); }

// ---------------- h0 = node_feats @ W_in + b_in  [N, H] ----------------
__global__ void k_h0(const float* __restrict__ nf, const float* __restrict__ Win,
                     const float* __restrict__ bin) {
    int idx = blockIdx.x * blockDim.x + threadIdx.x;
    if (idx >= N_NODES * H) return;
    int n = idx / H, c = idx % H;
    const float* x = nf + n * FN;
    float acc = bin[c];
#pragma unroll
    for (int k = 0; k < FN; k++) acc += x[k] * Win[k * H + c];
    g_h[idx] = acc;
}

// ---------------- RH = relu(edge_feats @ ee_W1 + ee_b1)  [E, H] ----------------
__global__ void k_rh(const float* __restrict__ ef, const float* __restrict__ W1,
                     const float* __restrict__ b1) {
    int idx = blockIdx.x * blockDim.x + threadIdx.x;
    if (idx >= N_EDGES * H) return;
    int e = idx / H, c = idx % H;
    const float* x = ef + e * FE;
    float acc = b1[c];
#pragma unroll
    for (int k = 0; k < FE; k++) acc += x[k] * W1[k * H + c];
    g_RH[idx] = fmaxf(acc, 0.0f);
}

// ---------------- A = RH @ ee_W2 + ee_b2   (M=E, N=5329, K=73) ----------------
// 64x64 output tile per block, 256 threads, 4x4 microtile, float4 smem reads.
__global__ __launch_bounds__(256) void k_gemmA(const float* __restrict__ W2,
                                               const float* __restrict__ b2) {
    __shared__ __align__(16) float As[73][64];   // As[k][m]
    __shared__ __align__(16) float Bs[73][64];   // Bs[k][n]
    int tid = threadIdx.x;
    int m0 = blockIdx.y * 64;
    int n0 = blockIdx.x * 64;

    // load A-tile (RH rows, coalesced along k) and transpose into smem
    for (int i = tid; i < 64 * 73; i += 256) {
        int m = i / 73, k = i % 73;
        As[k][m] = g_RH[(size_t)(m0 + m) * H + k];
    }
    // load B-tile (coalesced along n), zero-pad past 5329
    for (int i = tid; i < 73 * 64; i += 256) {
        int k = i / 64, n = i % 64;
        int col = n0 + n;
        Bs[k][n] = (col < HH) ? W2[(size_t)k * HH + col] : 0.0f;
    }
    __syncthreads();

    int tm = tid % 16, tn = tid / 16;
    float acc[4][4];
#pragma unroll
    for (int i = 0; i < 4; i++)
#pragma unroll
        for (int j = 0; j < 4; j++) acc[i][j] = 0.0f;

#pragma unroll 8
    for (int k = 0; k < 73; k++) {
        float4 a = *reinterpret_cast<const float4*>(&As[k][tm * 4]);
        float4 b = *reinterpret_cast<const float4*>(&Bs[k][tn * 4]);
        float av[4] = {a.x, a.y, a.z, a.w};
        float bv[4] = {b.x, b.y, b.z, b.w};
#pragma unroll
        for (int i = 0; i < 4; i++)
#pragma unroll
            for (int j = 0; j < 4; j++) acc[i][j] += av[i] * bv[j];
    }

#pragma unroll
    for (int i = 0; i < 4; i++) {
        int row = m0 + tm * 4 + i;
        size_t base = (size_t)row * HH;
#pragma unroll
        for (int j = 0; j < 4; j++) {
            int col = n0 + tn * 4 + j;
            if (col < HH) g_A[base + col] = acc[i][j] + b2[col];
        }
    }
}

// ---------------- zero agg ----------------
__global__ void k_zero() {
    int i = blockIdx.x * blockDim.x + threadIdx.x;
    if (i < N_NODES * H) g_agg[i] = 0.0f;
}

// ---------------- messages: m_e = A_e @ h[src], scatter-add to agg[tgt] ----------
__global__ void k_msg(const int* __restrict__ Esrc, const int* __restrict__ Etgt) {
    int e = blockIdx.x;
    __shared__ float hsv[H];
    int tid = threadIdx.x;
    int src = Esrc[e], tgt = Etgt[e];
    if (tid < H) hsv[tid] = g_h[(size_t)src * H + tid];
    __syncthreads();
    const float* Ae = g_A + (size_t)e * HH;
    int lane = tid & 31, w = tid >> 5;
    for (int i = w; i < H; i += 4) {
        const float* row = Ae + i * H;
        float acc = 0.0f;
        for (int j = lane; j < H; j += 32) acc += row[j] * hsv[j];
#pragma unroll
        for (int o = 16; o; o >>= 1) acc += __shfl_down_sync(0xffffffffu, acc, o);
        if (lane == 0) atomicAdd(&g_agg[(size_t)tgt * H + i], acc);
    }
}

// ---------------- GRU cell update (in place on g_h) ----------------
// block = 256 threads = 8 warps, handles 64 nodes; warp w covers channels w, w+8, ...
// lane covers nodes lane and lane+32 of the tile (agg/h staged in smem).
__global__ __launch_bounds__(256) void k_gru(const float* __restrict__ Wih,
                                             const float* __restrict__ Whh,
                                             const float* __restrict__ bih,
                                             const float* __restrict__ bhh) {
    __shared__ float ags[64 * H];
    __shared__ float hs[64 * H];
    int tid = threadIdx.x;
    int n0 = blockIdx.x * 64;
    for (int i = tid; i < 64 * H; i += 256) {
        ags[i] = g_agg[(size_t)n0 * H + i];
        hs[i]  = g_h[(size_t)n0 * H + i];
    }
    __syncthreads();
    int lane = tid & 31, w = tid >> 5;
    const float* a0 = ags + lane * H;
    const float* h0 = hs + lane * H;
    const float* a1 = ags + (lane + 32) * H;
    const float* h1 = hs + (lane + 32) * H;

    for (int c = w; c < H; c += 8) {
        const float* wir = Wih + (size_t)c * H;
        const float* wiz = Wih + (size_t)(H + c) * H;
        const float* win = Wih + (size_t)(2 * H + c) * H;
        const float* whr = Whh + (size_t)c * H;
        const float* whz = Whh + (size_t)(H + c) * H;
        const float* whn = Whh + (size_t)(2 * H + c) * H;
        float ir0 = 0, iz0 = 0, in0 = 0, hr0 = 0, hz0 = 0, hn0 = 0;
        float ir1 = 0, iz1 = 0, in1 = 0, hr1 = 0, hz1 = 0, hn1 = 0;
        for (int j = 0; j < H; j++) {
            float w1 = __ldg(&wir[j]), w2 = __ldg(&wiz[j]), w3 = __ldg(&win[j]);
            float w4 = __ldg(&whr[j]), w5 = __ldg(&whz[j]), w6 = __ldg(&whn[j]);
            float av = a0[j], hv = h0[j];
            ir0 += w1 * av; iz0 += w2 * av; in0 += w3 * av;
            hr0 += w4 * hv; hz0 += w5 * hv; hn0 += w6 * hv;
            av = a1[j]; hv = h1[j];
            ir1 += w1 * av; iz1 += w2 * av; in1 += w3 * av;
            hr1 += w4 * hv; hz1 += w5 * hv; hn1 += w6 * hv;
        }
        float br = bih[c] + bhh[c];
        float bz = bih[H + c] + bhh[H + c];
        float bin_ = bih[2 * H + c], bhn = bhh[2 * H + c];

        float r = sigf(ir0 + hr0 + br);
        float z = sigf(iz0 + hz0 + bz);
        float nn = tanhf(in0 + bin_ + r * (hn0 + bhn));
        g_h[(size_t)(n0 + lane) * H + c] = (1.0f - z) * nn + z * h0[c];

        r = sigf(ir1 + hr1 + br);
        z = sigf(iz1 + hz1 + bz);
        nn = tanhf(in1 + bin_ + r * (hn1 + bhn));
        g_h[(size_t)(n0 + lane + 32) * H + c] = (1.0f - z) * nn + z * h1[c];
    }
}

// ---------------- Set2Set: one block per batch segment, all 12 steps fused -------
// gates = hh @ (Wih[:, :H] + Whh)^T + r @ Wih[:, H:]^T + (bih + bhh)
#define EVMAX 2048
__global__ __launch_bounds__(256) void k_s2s(const float* __restrict__ Wih,
                                             const float* __restrict__ Whh,
                                             const float* __restrict__ bih,
                                             const float* __restrict__ bhh,
                                             const float* __restrict__ Wout,
                                             const float* __restrict__ bout,
                                             const int* __restrict__ batch,
                                             float* __restrict__ out) {
    extern __shared__ float sm[];
    float* Wa    = sm;                   // [292*73]
    float* Wb    = Wa + 292 * 73;        // [292*73]
    float* bias  = Wb + 292 * 73;        // [292]
    float* gates = bias + 292;           // [292]
    float* hh    = gates + 292;          // [73]
    float* cc    = hh + 73;              // [73]
    float* rr    = cc + 73;              // [73]
    float* ev    = rr + 73;              // [EVMAX]
    float* red   = ev + EVMAX;           // [34]

    int tid = threadIdx.x;
    int b = blockIdx.x;

    for (int i = tid; i < 292 * 73; i += 256) {
        int g = i / 73, k = i % 73;
        Wa[i] = Wih[(size_t)g * 146 + k] + Whh[(size_t)g * 73 + k];
        Wb[i] = Wih[(size_t)g * 146 + 73 + k];
    }
    for (int i = tid; i < 292; i += 256) bias[i] = bih[i] + bhh[i];
    if (tid < H) { hh[tid] = 0.0f; cc[tid] = 0.0f; rr[tid] = 0.0f; }

    // segment bounds via binary search on sorted batch[]
    int lo = 0, hi = N_NODES;
    while (lo < hi) { int mid = (lo + hi) >> 1; if (batch[mid] < b) lo = mid + 1; else hi = mid; }
    int s0 = lo;
    hi = N_NODES;
    while (lo < hi) { int mid = (lo + hi) >> 1; if (batch[mid] < b + 1) lo = mid + 1; else hi = mid; }
    int len = lo - s0;
    if (len > EVMAX) len = EVMAX;   // impossible for this input; defensive
    __syncthreads();

    int lane = tid & 31, w = tid >> 5;

    for (int t = 0; t < T_S2S; t++) {
        // LSTM gates
        for (int g = tid; g < 292; g += 256) {
            const float* wa = Wa + g * 73;
            const float* wb = Wb + g * 73;
            float acc = bias[g];
            for (int k = 0; k < H; k++) acc += hh[k] * wa[k] + rr[k] * wb[k];
            gates[g] = acc;
        }
        __syncthreads();
        if (tid < H) {
            float ig = gates[tid], fg = gates[H + tid], gg = gates[2 * H + tid], og = gates[3 * H + tid];
            float c2 = sigf(fg) * cc[tid] + sigf(ig) * tanhf(gg);
            cc[tid] = c2;
            hh[tid] = sigf(og) * tanhf(c2);   // q = hh
        }
        __syncthreads();

        if (len > 0) {
            // attention logits e_n = <h_n, q>
            for (int n = w; n < len; n += 8) {
                const float* hrow = g_h + (size_t)(s0 + n) * H;
                float acc = 0.0f;
                for (int c = lane; c < H; c += 32) acc += hrow[c] * hh[c];
#pragma unroll
                for (int o = 16; o; o >>= 1) acc += __shfl_down_sync(0xffffffffu, acc, o);
                if (lane == 0) ev[n] = acc;
            }
            __syncthreads();
            // segment max
            float m = -INFINITY;
            for (int n = tid; n < len; n += 256) m = fmaxf(m, ev[n]);
#pragma unroll
            for (int o = 16; o; o >>= 1) m = fmaxf(m, __shfl_xor_sync(0xffffffffu, m, o));
            if (lane == 0) red[w] = m;
            __syncthreads();
            if (tid == 0) {
                float mm = red[0];
                for (int i = 1; i < 8; i++) mm = fmaxf(mm, red[i]);
                red[32] = mm;
            }
            __syncthreads();
            m = red[32];
            // exp + segment sum
            float s = 0.0f;
            for (int n = tid; n < len; n += 256) { float a = expf(ev[n] - m); ev[n] = a; s += a; }
#pragma unroll
            for (int o = 16; o; o >>= 1) s += __shfl_xor_sync(0xffffffffu, s, o);
            if (lane == 0) red[w] = s;
            __syncthreads();
            if (tid == 0) {
                float ss = 0.0f;
                for (int i = 0; i < 8; i++) ss += red[i];
                red[33] = ss;
            }
            __syncthreads();
            float inv = 1.0f / red[33];
            // readout r_c = sum_n a_n h[n][c]
            if (tid < H) {
                float acc = 0.0f;
                for (int n = 0; n < len; n++) acc += ev[n] * g_h[(size_t)(s0 + n) * H + tid];
                rr[tid] = acc * inv;
            }
            __syncthreads();
        }
    }

    if (tid == 0) {
        float s = bout[0];
        for (int c = 0; c < H; c++) s += hh[c] * Wout[c];
        out[b] = s;
    }
}

// ---------------- launch ----------------
extern "C" void kernel_launch(void* const* d_in, const int* in_sizes, int n_in,
                              void* d_out, int out_size) {
    const float* nf   = (const float*)d_in[0];
    const float* ef   = (const float*)d_in[1];
    const float* Win  = (const float*)d_in[2];
    const float* bin  = (const float*)d_in[3];
    const float* W1   = (const float*)d_in[4];
    const float* b1   = (const float*)d_in[5];
    const float* W2   = (const float*)d_in[6];
    const float* b2   = (const float*)d_in[7];
    const float* gWih = (const float*)d_in[8];
    const float* gWhh = (const float*)d_in[9];
    const float* gbih = (const float*)d_in[10];
    const float* gbhh = (const float*)d_in[11];
    const float* lWih = (const float*)d_in[12];
    const float* lWhh = (const float*)d_in[13];
    const float* lbih = (const float*)d_in[14];
    const float* lbhh = (const float*)d_in[15];
    const float* Wout = (const float*)d_in[16];
    const float* bout = (const float*)d_in[17];
    const int* Esrc   = (const int*)d_in[18];
    const int* Etgt   = (const int*)d_in[19];
    const int* batch  = (const int*)d_in[20];
    float* out = (float*)d_out;

    k_h0<<<(N_NODES * H + 255) / 256, 256>>>(nf, Win, bin);
    k_rh<<<(N_EDGES * H + 255) / 256, 256>>>(ef, W1, b1);

    dim3 ggrid((HH + 63) / 64, N_EDGES / 64);
    k_gemmA<<<ggrid, 256>>>(W2, b2);

    for (int t = 0; t < T_MP; t++) {
        k_zero<<<(N_NODES * H + 255) / 256, 256>>>();
        k_msg<<<N_EDGES, 128>>>(Esrc, Etgt);
        k_gru<<<N_NODES / 64, 256>>>(gWih, gWhh, gbih, gbhh);
    }

    size_t smem = (size_t)(2 * 292 * 73 + 292 + 292 + 3 * 73 + EVMAX + 34) * sizeof(float);
    cudaFuncSetAttribute(k_s2s, cudaFuncAttributeMaxDynamicSharedMemorySize, (int)smem);
    k_s2s<<<NB, 256, smem>>>(lWih, lWhh, lbih, lbhh, Wout, bout, batch, out);
}

// round 2
// speedup vs baseline: 1.7302x; 1.7302x over previous
#include <cuda_runtime.h>
#include <math.h>

#define N_NODES 8192
#define N_EDGES 32768
#define FN 32
#define FE 16
#define H 73
#define HH (H*H)            // 5329
#define TW (H*(H+1))        // 5402 = 73*74, T2 row width
#define G3 (3*H)            // 219
#define NB 64
#define T_MP 3
#define T_S2S 12

// ---------------- device scratch ----------------
__device__ float g_h[N_NODES * H];
__device__ float g_RH[N_EDGES * H];
__device__ float g_agg[N_NODES * H];
__device__ float g_T2[(size_t)N_NODES * TW];      // 177 MB
__device__ float g_W2e[H * TW];                   // 1.58 MB
__device__ float g_WihT[H * G3];
__device__ float g_WhhT[H * G3];
__device__ float g_GG1[N_NODES * G3];
__device__ float g_GG2[N_NODES * G3];
__device__ int g_cnt[N_NODES];
__device__ int g_off[N_NODES + 1];
__device__ int g_cur[N_NODES];
__device__ int g_eord[N_EDGES];

__device__ __forceinline__ float sigf(float x) { return 1.0f / (1.0f + expf(-x)); }

// ---------------- h0 = node_feats @ W_in + b_in ----------------
__global__ void k_h0(const float* __restrict__ nf, const float* __restrict__ Win,
                     const float* __restrict__ bin) {
    int idx = blockIdx.x * blockDim.x + threadIdx.x;
    if (idx >= N_NODES * H) return;
    int n = idx / H, c = idx % H;
    const float* x = nf + n * FN;
    float acc = bin[c];
#pragma unroll
    for (int k = 0; k < FN; k++) acc += x[k] * Win[k * H + c];
    g_h[idx] = acc;
}

// ---------------- RH = relu(edge_feats @ ee_W1 + ee_b1) ----------------
__global__ void k_rh(const float* __restrict__ ef, const float* __restrict__ W1,
                     const float* __restrict__ b1) {
    int idx = blockIdx.x * blockDim.x + threadIdx.x;
    if (idx >= N_EDGES * H) return;
    int e = idx / H, c = idx % H;
    const float* x = ef + e * FE;
    float acc = b1[c];
#pragma unroll
    for (int k = 0; k < FE; k++) acc += x[k] * W1[k * H + c];
    g_RH[idx] = fmaxf(acc, 0.0f);
}

// ---------------- prep: W2ext  W2e[j, i*74+k] = W2[k, i*73+j]; k=73 row = b2 ------
__global__ void k_prepW2(const float* __restrict__ W2, const float* __restrict__ b2) {
    int idx = blockIdx.x * blockDim.x + threadIdx.x;
    if (idx >= H * TW) return;
    int j = idx / TW, c = idx % TW;
    int i = c / (H + 1), k = c % (H + 1);
    g_W2e[idx] = (k < H) ? W2[(size_t)k * HH + i * H + j] : b2[i * H + j];
}

// ---------------- prep: transposed GRU weights [73, 219] ----------------
__global__ void k_prepWT(const float* __restrict__ Wih, const float* __restrict__ Whh) {
    int idx = blockIdx.x * blockDim.x + threadIdx.x;
    if (idx >= H * G3) return;
    int k = idx / G3, g = idx % G3;
    g_WihT[idx] = Wih[(size_t)g * H + k];
    g_WhhT[idx] = Whh[(size_t)g * H + k];
}

// ---------------- counting sort of edges by src ----------------
__global__ void k_zcnt() {
    int i = blockIdx.x * blockDim.x + threadIdx.x;
    if (i < N_NODES) g_cnt[i] = 0;
}
__global__ void k_hist(const int* __restrict__ Esrc) {
    int e = blockIdx.x * blockDim.x + threadIdx.x;
    if (e < N_EDGES) atomicAdd(&g_cnt[Esrc[e]], 1);
}
__global__ __launch_bounds__(1024) void k_scan() {
    __shared__ int sm_[1024];
    int tid = threadIdx.x;
    int base = tid * 8;
    int v[8], s = 0;
#pragma unroll
    for (int i = 0; i < 8; i++) { v[i] = g_cnt[base + i]; s += v[i]; }
    sm_[tid] = s;
    __syncthreads();
    for (int off = 1; off < 1024; off <<= 1) {
        int t = (tid >= off) ? sm_[tid - off] : 0;
        __syncthreads();
        sm_[tid] += t;
        __syncthreads();
    }
    int run = sm_[tid] - s;
#pragma unroll
    for (int i = 0; i < 8; i++) {
        g_off[base + i] = run;
        g_cur[base + i] = run;
        run += v[i];
    }
    if (tid == 1023) g_off[N_NODES] = run;
}
__global__ void k_scatterE(const int* __restrict__ Esrc) {
    int e = blockIdx.x * blockDim.x + threadIdx.x;
    if (e >= N_EDGES) return;
    int p = atomicAdd(&g_cur[Esrc[e]], 1);
    g_eord[p] = e;
}

// ---------------- generic SGEMM: C[M,N] = A[M,K] @ B[K,N], M multiple of 128 ------
// 128x128 tile, 256 threads, 8x8 microtile, whole-K strip in smem (K<=146).
__global__ __launch_bounds__(256) void k_gemm(const float* __restrict__ A,
                                              const float* __restrict__ B,
                                              float* __restrict__ C,
                                              int N, int K) {
    extern __shared__ float smg[];
    const int LD = 132;
    float* As = smg;           // [K][132]
    float* Bs = smg + K * LD;  // [K][132]
    int tid = threadIdx.x;
    int m0 = blockIdx.y * 128;
    int n0 = blockIdx.x * 128;

    for (int idx = tid; idx < 128 * K; idx += 256) {
        int m = idx / K, k = idx - m * K;
        As[k * LD + m] = A[(size_t)(m0 + m) * K + k];
    }
    for (int idx = tid; idx < K * 128; idx += 256) {
        int k = idx >> 7, n = idx & 127;
        int col = n0 + n;
        Bs[k * LD + n] = (col < N) ? B[(size_t)k * N + col] : 0.0f;
    }
    __syncthreads();

    int tm = tid & 15, tn = tid >> 4;
    float acc[8][8];
#pragma unroll
    for (int i = 0; i < 8; i++)
#pragma unroll
        for (int j = 0; j < 8; j++) acc[i][j] = 0.0f;

    for (int k = 0; k < K; k++) {
        const float* arow = As + k * LD;
        const float* brow = Bs + k * LD;
        float4 a0 = *reinterpret_cast<const float4*>(arow + tm * 4);
        float4 a1 = *reinterpret_cast<const float4*>(arow + 64 + tm * 4);
        float4 b0 = *reinterpret_cast<const float4*>(brow + tn * 4);
        float4 b1 = *reinterpret_cast<const float4*>(brow + 64 + tn * 4);
        float av[8] = {a0.x, a0.y, a0.z, a0.w, a1.x, a1.y, a1.z, a1.w};
        float bv[8] = {b0.x, b0.y, b0.z, b0.w, b1.x, b1.y, b1.z, b1.w};
#pragma unroll
        for (int i = 0; i < 8; i++)
#pragma unroll
            for (int j = 0; j < 8; j++) acc[i][j] += av[i] * bv[j];
    }

#pragma unroll
    for (int i = 0; i < 8; i++) {
        int r = m0 + ((i < 4) ? tm * 4 + i : 64 + tm * 4 + (i - 4));
        size_t rb = (size_t)r * N;
#pragma unroll
        for (int j = 0; j < 8; j++) {
            int c = n0 + ((j < 4) ? tn * 4 + j : 64 + tn * 4 + (j - 4));
            if (c < N) C[rb + c] = acc[i][j];
        }
    }
}

// ---------------- zero agg ----------------
__global__ void k_zero() {
    int i = blockIdx.x * blockDim.x + threadIdx.x;
    if (i < N_NODES * H) g_agg[i] = 0.0f;
}

// ---------------- messages via T2: one block per src ----------------
// m_e[i] = sum_k RH[e,k] * T2[src, i*74+k] + T2[src, i*74+73]; scatter-add to tgt.
__global__ __launch_bounds__(128) void k_msg2(const int* __restrict__ Etgt) {
    int src = blockIdx.x;
    int s0 = g_off[src], s1 = g_off[src + 1];
    if (s0 == s1) return;
    __shared__ float rh[8][H];
    __shared__ int tgts[8];
    int tid = threadIdx.x;
    const float* trow = g_T2 + (size_t)src * TW;

    for (int base = s0; base < s1; base += 8) {
        int ne = min(8, s1 - base);
        for (int idx = tid; idx < ne * H; idx += 128) {
            int el = idx / H, k = idx - el * H;
            rh[el][k] = g_RH[(size_t)g_eord[base + el] * H + k];
        }
        if (tid < ne) tgts[tid] = Etgt[g_eord[base + tid]];
        __syncthreads();
        if (tid < H) {
            const float* tp = trow + tid * (H + 1);
            float bterm = tp[H];
            float acc[8];
#pragma unroll
            for (int e = 0; e < 8; e++) acc[e] = bterm;
            for (int k = 0; k < H; k++) {
                float v = tp[k];
#pragma unroll
                for (int e = 0; e < 8; e++)
                    if (e < ne) acc[e] += rh[e][k] * v;
            }
#pragma unroll
            for (int e = 0; e < 8; e++)
                if (e < ne) atomicAdd(&g_agg[(size_t)tgts[e] * H + tid], acc[e]);
        }
        __syncthreads();
    }
}

// ---------------- GRU pointwise ----------------
__global__ void k_grupt(const float* __restrict__ bih, const float* __restrict__ bhh) {
    int idx = blockIdx.x * blockDim.x + threadIdx.x;
    if (idx >= N_NODES * H) return;
    int n = idx / H, c = idx - n * H;
    const float* G1 = g_GG1 + (size_t)n * G3;
    const float* G2 = g_GG2 + (size_t)n * G3;
    float r = sigf(G1[c] + G2[c] + bih[c] + bhh[c]);
    float z = sigf(G1[H + c] + G2[H + c] + bih[H + c] + bhh[H + c]);
    float nn = tanhf(G1[2 * H + c] + bih[2 * H + c] + r * (G2[2 * H + c] + bhh[2 * H + c]));
    g_h[idx] = (1.0f - z) * nn + z * g_h[idx];
}

// ---------------- Set2Set (fused 12 steps, one block per batch) ----------------
#define EVMAX 2048
__global__ __launch_bounds__(256) void k_s2s(const float* __restrict__ Wih,
                                             const float* __restrict__ Whh,
                                             const float* __restrict__ bih,
                                             const float* __restrict__ bhh,
                                             const float* __restrict__ Wout,
                                             const float* __restrict__ bout,
                                             const int* __restrict__ batch,
                                             float* __restrict__ out) {
    extern __shared__ float sm[];
    float* Wa    = sm;                   // [292*73]
    float* Wb    = Wa + 292 * 73;        // [292*73]
    float* bias  = Wb + 292 * 73;        // [292]
    float* gates = bias + 292;           // [292]
    float* hh    = gates + 292;          // [73]
    float* cc    = hh + 73;              // [73]
    float* rr    = cc + 73;              // [73]
    float* ev    = rr + 73;              // [EVMAX]
    float* red   = ev + EVMAX;           // [34]

    int tid = threadIdx.x;
    int b = blockIdx.x;

    for (int i = tid; i < 292 * 73; i += 256) {
        int g = i / 73, k = i % 73;
        Wa[i] = Wih[(size_t)g * 146 + k] + Whh[(size_t)g * 73 + k];
        Wb[i] = Wih[(size_t)g * 146 + 73 + k];
    }
    for (int i = tid; i < 292; i += 256) bias[i] = bih[i] + bhh[i];
    if (tid < H) { hh[tid] = 0.0f; cc[tid] = 0.0f; rr[tid] = 0.0f; }

    int lo = 0, hi = N_NODES;
    while (lo < hi) { int mid = (lo + hi) >> 1; if (batch[mid] < b) lo = mid + 1; else hi = mid; }
    int s0 = lo;
    hi = N_NODES;
    while (lo < hi) { int mid = (lo + hi) >> 1; if (batch[mid] < b + 1) lo = mid + 1; else hi = mid; }
    int len = lo - s0;
    if (len > EVMAX) len = EVMAX;
    __syncthreads();

    int lane = tid & 31, w = tid >> 5;

    for (int t = 0; t < T_S2S; t++) {
        for (int g = tid; g < 292; g += 256) {
            const float* wa = Wa + g * 73;
            const float* wb = Wb + g * 73;
            float acc = bias[g];
            for (int k = 0; k < H; k++) acc += hh[k] * wa[k] + rr[k] * wb[k];
            gates[g] = acc;
        }
        __syncthreads();
        if (tid < H) {
            float ig = gates[tid], fg = gates[H + tid], gg = gates[2 * H + tid], og = gates[3 * H + tid];
            float c2 = sigf(fg) * cc[tid] + sigf(ig) * tanhf(gg);
            cc[tid] = c2;
            hh[tid] = sigf(og) * tanhf(c2);
        }
        __syncthreads();

        if (len > 0) {
            for (int n = w; n < len; n += 8) {
                const float* hrow = g_h + (size_t)(s0 + n) * H;
                float acc = 0.0f;
                for (int c = lane; c < H; c += 32) acc += hrow[c] * hh[c];
#pragma unroll
                for (int o = 16; o; o >>= 1) acc += __shfl_down_sync(0xffffffffu, acc, o);
                if (lane == 0) ev[n] = acc;
            }
            __syncthreads();
            float m = -INFINITY;
            for (int n = tid; n < len; n += 256) m = fmaxf(m, ev[n]);
#pragma unroll
            for (int o = 16; o; o >>= 1) m = fmaxf(m, __shfl_xor_sync(0xffffffffu, m, o));
            if (lane == 0) red[w] = m;
            __syncthreads();
            if (tid == 0) {
                float mm = red[0];
                for (int i = 1; i < 8; i++) mm = fmaxf(mm, red[i]);
                red[32] = mm;
            }
            __syncthreads();
            m = red[32];
            float s = 0.0f;
            for (int n = tid; n < len; n += 256) { float a = expf(ev[n] - m); ev[n] = a; s += a; }
#pragma unroll
            for (int o = 16; o; o >>= 1) s += __shfl_xor_sync(0xffffffffu, s, o);
            if (lane == 0) red[w] = s;
            __syncthreads();
            if (tid == 0) {
                float ss = 0.0f;
                for (int i = 0; i < 8; i++) ss += red[i];
                red[33] = ss;
            }
            __syncthreads();
            float inv = 1.0f / red[33];
            if (tid < H) {
                float acc = 0.0f;
                for (int n = 0; n < len; n++) acc += ev[n] * g_h[(size_t)(s0 + n) * H + tid];
                rr[tid] = acc * inv;
            }
            __syncthreads();
        }
    }

    if (tid == 0) {
        float s = bout[0];
        for (int c = 0; c < H; c++) s += hh[c] * Wout[c];
        out[b] = s;
    }
}

// ---------------- launch ----------------
extern "C" void kernel_launch(void* const* d_in, const int* in_sizes, int n_in,
                              void* d_out, int out_size) {
    const float* nf   = (const float*)d_in[0];
    const float* ef   = (const float*)d_in[1];
    const float* Win  = (const float*)d_in[2];
    const float* bin  = (const float*)d_in[3];
    const float* W1   = (const float*)d_in[4];
    const float* b1   = (const float*)d_in[5];
    const float* W2   = (const float*)d_in[6];
    const float* b2   = (const float*)d_in[7];
    const float* gWih = (const float*)d_in[8];
    const float* gWhh = (const float*)d_in[9];
    const float* gbih = (const float*)d_in[10];
    const float* gbhh = (const float*)d_in[11];
    const float* lWih = (const float*)d_in[12];
    const float* lWhh = (const float*)d_in[13];
    const float* lbih = (const float*)d_in[14];
    const float* lbhh = (const float*)d_in[15];
    const float* Wout = (const float*)d_in[16];
    const float* bout = (const float*)d_in[17];
    const int* Esrc   = (const int*)d_in[18];
    const int* Etgt   = (const int*)d_in[19];
    const int* batch  = (const int*)d_in[20];
    float* out = (float*)d_out;

    float *p_h, *p_T2, *p_W2e, *p_agg, *p_WihT, *p_WhhT, *p_GG1, *p_GG2;
    cudaGetSymbolAddress((void**)&p_h, g_h);
    cudaGetSymbolAddress((void**)&p_T2, g_T2);
    cudaGetSymbolAddress((void**)&p_W2e, g_W2e);
    cudaGetSymbolAddress((void**)&p_agg, g_agg);
    cudaGetSymbolAddress((void**)&p_WihT, g_WihT);
    cudaGetSymbolAddress((void**)&p_WhhT, g_WhhT);
    cudaGetSymbolAddress((void**)&p_GG1, g_GG1);
    cudaGetSymbolAddress((void**)&p_GG2, g_GG2);

    int gemm_smem = 2 * H * 132 * sizeof(float);  // 77 KB (K=73)
    cudaFuncSetAttribute(k_gemm, cudaFuncAttributeMaxDynamicSharedMemorySize, gemm_smem);
    size_t s2s_smem = (size_t)(2 * 292 * 73 + 292 + 292 + 3 * 73 + EVMAX + 34) * sizeof(float);
    cudaFuncSetAttribute(k_s2s, cudaFuncAttributeMaxDynamicSharedMemorySize, (int)s2s_smem);

    // launch order chosen so launch index 5 (ncu -s 5) is the first T2 GEMM
    k_prepW2<<<(H * TW + 255) / 256, 256>>>(W2, b2);                 // 0
    k_h0<<<(N_NODES * H + 255) / 256, 256>>>(nf, Win, bin);          // 1
    k_rh<<<(N_EDGES * H + 255) / 256, 256>>>(ef, W1, b1);            // 2
    k_zcnt<<<(N_NODES + 255) / 256, 256>>>();                        // 3
    k_hist<<<(N_EDGES + 255) / 256, 256>>>(Esrc);                    // 4

    dim3 gT((TW + 127) / 128, N_NODES / 128);
    dim3 gG((G3 + 127) / 128, N_NODES / 128);

    k_gemm<<<gT, 256, gemm_smem>>>(p_h, p_W2e, p_T2, TW, H);         // 5 (step 0 T2)

    k_scan<<<1, 1024>>>();                                            // 6
    k_scatterE<<<(N_EDGES + 255) / 256, 256>>>(Esrc);                // 7
    k_prepWT<<<(H * G3 + 255) / 256, 256>>>(gWih, gWhh);             // 8

    for (int t = 0; t < T_MP; t++) {
        if (t > 0)
            k_gemm<<<gT, 256, gemm_smem>>>(p_h, p_W2e, p_T2, TW, H);
        k_zero<<<(N_NODES * H + 255) / 256, 256>>>();
        k_msg2<<<N_NODES, 128>>>(Etgt);
        k_gemm<<<gG, 256, gemm_smem>>>(p_agg, p_WihT, p_GG1, G3, H);
        k_gemm<<<gG, 256, gemm_smem>>>(p_h, p_WhhT, p_GG2, G3, H);
        k_grupt<<<(N_NODES * H + 255) / 256, 256>>>(gbih, gbhh);
    }

    k_s2s<<<NB, 256, s2s_smem>>>(lWih, lWhh, lbih, lbhh, Wout, bout, batch, out);
}

// round 3
// speedup vs baseline: 3.2096x; 1.8550x over previous
#include <cuda_runtime.h>
#include <cuda_fp16.h>
#include <math.h>

#define N_NODES 8192
#define N_EDGES 32768
#define FN 32
#define FE 16
#define H 73
#define HH (H*H)            // 5329
#define KP 80               // padded K for MMA (5 x k16)
#define TW 5402             // T2 row width (real) = 73*74
#define TWP 5504            // padded to 43*128
#define G3 219
#define G3P 256             // padded to 2*128
#define GLD 220             // GG ldc (even for float2 stores)
#define NB 64
#define T_MP 3
#define T_S2S 12

// ---------------- device scratch ----------------
__device__ float g_h[N_NODES * H];
__device__ __half g_h16[N_NODES * KP];
__device__ __half g_agg16[N_NODES * KP];
__device__ float g_RH[N_EDGES * H];
__device__ float g_agg[N_NODES * H];
__device__ float g_T2[(size_t)N_NODES * TW];      // 177 MB
__device__ __half g_W2e[KP * TWP];
__device__ __half g_WihT[KP * G3P];
__device__ __half g_WhhT[KP * G3P];
__device__ float g_GG1[N_NODES * GLD];
__device__ float g_GG2[N_NODES * GLD];
__device__ int g_cnt[N_NODES];
__device__ int g_off[N_NODES + 1];
__device__ int g_cur[N_NODES];
__device__ int g_eord[N_EDGES];

__device__ __forceinline__ float sigf(float x) { return 1.0f / (1.0f + expf(-x)); }

__device__ __forceinline__ void ldsm_x4(unsigned &r0, unsigned &r1, unsigned &r2, unsigned &r3, unsigned addr) {
    asm volatile("ldmatrix.sync.aligned.m8n8.x4.shared.b16 {%0,%1,%2,%3},[%4];"
                 : "=r"(r0), "=r"(r1), "=r"(r2), "=r"(r3) : "r"(addr));
}
__device__ __forceinline__ void ldsm_x4t(unsigned &r0, unsigned &r1, unsigned &r2, unsigned &r3, unsigned addr) {
    asm volatile("ldmatrix.sync.aligned.m8n8.x4.trans.shared.b16 {%0,%1,%2,%3},[%4];"
                 : "=r"(r0), "=r"(r1), "=r"(r2), "=r"(r3) : "r"(addr));
}
__device__ __forceinline__ void mma16816(float* d, const unsigned* a, unsigned b0, unsigned b1) {
    asm volatile("mma.sync.aligned.m16n8k16.row.col.f32.f16.f16.f32 "
                 "{%0,%1,%2,%3},{%4,%5,%6,%7},{%8,%9},{%0,%1,%2,%3};"
                 : "+f"(d[0]), "+f"(d[1]), "+f"(d[2]), "+f"(d[3])
                 : "r"(a[0]), "r"(a[1]), "r"(a[2]), "r"(a[3]), "r"(b0), "r"(b1));
}

// ---------------- h0 = node_feats @ W_in + b_in (fp32 + fp16 copies) ----------------
__global__ void k_h0(const float* __restrict__ nf, const float* __restrict__ Win,
                     const float* __restrict__ bin) {
    int idx = blockIdx.x * blockDim.x + threadIdx.x;
    if (idx >= N_NODES * KP) return;
    int n = idx / KP, c = idx % KP;
    if (c >= H) { g_h16[idx] = __float2half(0.0f); return; }
    const float* x = nf + n * FN;
    float acc = bin[c];
#pragma unroll
    for (int k = 0; k < FN; k++) acc += x[k] * Win[k * H + c];
    g_h[n * H + c] = acc;
    g_h16[idx] = __float2half(acc);
}

// ---------------- RH = relu(edge_feats @ ee_W1 + ee_b1) ----------------
__global__ void k_rh(const float* __restrict__ ef, const float* __restrict__ W1,
                     const float* __restrict__ b1) {
    int idx = blockIdx.x * blockDim.x + threadIdx.x;
    if (idx >= N_EDGES * H) return;
    int e = idx / H, c = idx % H;
    const float* x = ef + e * FE;
    float acc = b1[c];
#pragma unroll
    for (int k = 0; k < FE; k++) acc += x[k] * W1[k * H + c];
    g_RH[idx] = fmaxf(acc, 0.0f);
}

// ---------------- prep: W2e16[j, i*74+kk] = W2[kk, i*73+j] (kk<73) / b2[i*73+j] (kk=73)
__global__ void k_prepW2(const float* __restrict__ W2, const float* __restrict__ b2) {
    int idx = blockIdx.x * blockDim.x + threadIdx.x;
    if (idx >= KP * TWP) return;
    int j = idx / TWP, c = idx % TWP;
    float v = 0.0f;
    if (j < H && c < TW) {
        int i = c / (H + 1), kk = c % (H + 1);
        v = (kk < H) ? W2[(size_t)kk * HH + i * H + j] : b2[i * H + j];
    }
    g_W2e[idx] = __float2half(v);
}

// ---------------- prep: transposed GRU weights, fp16, padded [80, 256] -------------
__global__ void k_prepWT(const float* __restrict__ Wih, const float* __restrict__ Whh) {
    int idx = blockIdx.x * blockDim.x + threadIdx.x;
    if (idx >= KP * G3P) return;
    int k = idx / G3P, g = idx % G3P;
    float a = 0.0f, b = 0.0f;
    if (k < H && g < G3) { a = Wih[(size_t)g * H + k]; b = Whh[(size_t)g * H + k]; }
    g_WihT[idx] = __float2half(a);
    g_WhhT[idx] = __float2half(b);
}

// ---------------- counting sort of edges by src ----------------
__global__ void k_zcnt() {
    int i = blockIdx.x * blockDim.x + threadIdx.x;
    if (i < N_NODES) g_cnt[i] = 0;
}
__global__ void k_hist(const int* __restrict__ Esrc) {
    int e = blockIdx.x * blockDim.x + threadIdx.x;
    if (e < N_EDGES) atomicAdd(&g_cnt[Esrc[e]], 1);
}
__global__ __launch_bounds__(1024) void k_scan() {
    __shared__ int sm_[1024];
    int tid = threadIdx.x;
    int base = tid * 8;
    int v[8], s = 0;
#pragma unroll
    for (int i = 0; i < 8; i++) { v[i] = g_cnt[base + i]; s += v[i]; }
    sm_[tid] = s;
    __syncthreads();
    for (int off = 1; off < 1024; off <<= 1) {
        int t = (tid >= off) ? sm_[tid - off] : 0;
        __syncthreads();
        sm_[tid] += t;
        __syncthreads();
    }
    int run = sm_[tid] - s;
#pragma unroll
    for (int i = 0; i < 8; i++) {
        g_off[base + i] = run;
        g_cur[base + i] = run;
        run += v[i];
    }
    if (tid == 1023) g_off[N_NODES] = run;
}
__global__ void k_scatterE(const int* __restrict__ Esrc) {
    int e = blockIdx.x * blockDim.x + threadIdx.x;
    if (e >= N_EDGES) return;
    int p = atomicAdd(&g_cur[Esrc[e]], 1);
    g_eord[p] = e;
}

// ---------------- fp16 tensor-core GEMM: C[M,N] = A[M,80] @ B[80,N] ----------------
// block 128x128, 256 threads, warp tile 32x64, whole K=80 strip in smem.
__global__ __launch_bounds__(256) void k_hgemm(const __half* __restrict__ A,
                                               const __half* __restrict__ B,
                                               float* __restrict__ C,
                                               int ldb, int ldc, int nreal) {
    __shared__ __align__(16) __half As[128][88];
    __shared__ __align__(16) __half Bs[KP][136];
    int tid = threadIdx.x;
    int m0 = blockIdx.y * 128;
    int n0 = blockIdx.x * 128;

    const uint4* Ag = reinterpret_cast<const uint4*>(A + (size_t)m0 * KP);
    for (int idx = tid; idx < 1280; idx += 256) {
        int r = idx / 10, c = idx % 10;
        *reinterpret_cast<uint4*>(&As[r][c * 8]) = Ag[idx];
    }
    for (int idx = tid; idx < 1280; idx += 256) {
        int k = idx >> 4, c = idx & 15;
        *reinterpret_cast<uint4*>(&Bs[k][c * 8]) =
            *reinterpret_cast<const uint4*>(B + (size_t)k * ldb + n0 + c * 8);
    }
    __syncthreads();

    int wid = tid >> 5, lane = tid & 31;
    int wm0 = (wid & 3) * 32;
    int wn0 = (wid >> 2) * 64;

    float acc[2][8][4];
#pragma unroll
    for (int i = 0; i < 2; i++)
#pragma unroll
        for (int j = 0; j < 8; j++)
#pragma unroll
            for (int q = 0; q < 4; q++) acc[i][j][q] = 0.0f;

    unsigned a_base = (unsigned)__cvta_generic_to_shared(&As[0][0]);
    unsigned b_base = (unsigned)__cvta_generic_to_shared(&Bs[0][0]);
    int lr = lane & 15, lc = (lane >> 4) * 8;

#pragma unroll
    for (int ks = 0; ks < 5; ks++) {
        int k0 = ks * 16;
        unsigned af[2][4];
#pragma unroll
        for (int mi = 0; mi < 2; mi++) {
            unsigned addr = a_base + (unsigned)(((wm0 + mi * 16 + lr) * 88 + k0 + lc) * 2);
            ldsm_x4(af[mi][0], af[mi][1], af[mi][2], af[mi][3], addr);
        }
        unsigned bf[4][4];
#pragma unroll
        for (int nj = 0; nj < 4; nj++) {
            unsigned addr = b_base + (unsigned)(((k0 + lr) * 136 + wn0 + nj * 16 + lc) * 2);
            ldsm_x4t(bf[nj][0], bf[nj][1], bf[nj][2], bf[nj][3], addr);
        }
#pragma unroll
        for (int mi = 0; mi < 2; mi++)
#pragma unroll
            for (int nj = 0; nj < 4; nj++) {
                mma16816(acc[mi][2 * nj], af[mi], bf[nj][0], bf[nj][1]);
                mma16816(acc[mi][2 * nj + 1], af[mi], bf[nj][2], bf[nj][3]);
            }
    }

    int gr = lane >> 2, gc = (lane & 3) * 2;
#pragma unroll
    for (int mi = 0; mi < 2; mi++) {
#pragma unroll
        for (int nj8 = 0; nj8 < 8; nj8++) {
            int col = n0 + wn0 + nj8 * 8 + gc;
#pragma unroll
            for (int rr = 0; rr < 2; rr++) {
                int row = m0 + wm0 + mi * 16 + gr + rr * 8;
                float v0 = acc[mi][nj8][rr * 2], v1 = acc[mi][nj8][rr * 2 + 1];
                if (col + 1 < nreal) {
                    float2 vv = make_float2(v0, v1);
                    *reinterpret_cast<float2*>(C + (size_t)row * ldc + col) = vv;
                } else if (col < nreal) {
                    C[(size_t)row * ldc + col] = v0;
                }
            }
        }
    }
}

// ---------------- zero agg ----------------
__global__ void k_zero() {
    int i = blockIdx.x * blockDim.x + threadIdx.x;
    if (i < N_NODES * H) g_agg[i] = 0.0f;
}

// ---------------- messages via T2 ----------------
__global__ __launch_bounds__(128) void k_msg2(const int* __restrict__ Etgt) {
    int src = blockIdx.x;
    int s0 = g_off[src], s1 = g_off[src + 1];
    if (s0 == s1) return;
    __shared__ float rh[8][H];
    __shared__ int tgts[8];
    int tid = threadIdx.x;
    const float* trow = g_T2 + (size_t)src * TW;

    for (int base = s0; base < s1; base += 8) {
        int ne = min(8, s1 - base);
        for (int idx = tid; idx < ne * H; idx += 128) {
            int el = idx / H, k = idx - el * H;
            rh[el][k] = g_RH[(size_t)g_eord[base + el] * H + k];
        }
        if (tid < ne) tgts[tid] = Etgt[g_eord[base + tid]];
        __syncthreads();
        if (tid < H) {
            const float* tp = trow + tid * (H + 1);
            float bterm = tp[H];
            float acc[8];
#pragma unroll
            for (int e = 0; e < 8; e++) acc[e] = bterm;
            for (int k = 0; k < H; k++) {
                float v = tp[k];
#pragma unroll
                for (int e = 0; e < 8; e++)
                    if (e < ne) acc[e] += rh[e][k] * v;
            }
#pragma unroll
            for (int e = 0; e < 8; e++)
                if (e < ne) atomicAdd(&g_agg[(size_t)tgts[e] * H + tid], acc[e]);
        }
        __syncthreads();
    }
}

// ---------------- convert agg to fp16 padded ----------------
__global__ void k_cvt_agg() {
    int idx = blockIdx.x * blockDim.x + threadIdx.x;
    if (idx >= N_NODES * KP) return;
    int n = idx / KP, c = idx % KP;
    g_agg16[idx] = __float2half((c < H) ? g_agg[n * H + c] : 0.0f);
}

// ---------------- GRU pointwise (also refresh h16) ----------------
__global__ void k_grupt(const float* __restrict__ bih, const float* __restrict__ bhh) {
    int idx = blockIdx.x * blockDim.x + threadIdx.x;
    if (idx >= N_NODES * KP) return;
    int n = idx / KP, c = idx % KP;
    if (c >= H) { g_h16[idx] = __float2half(0.0f); return; }
    const float* G1 = g_GG1 + (size_t)n * GLD;
    const float* G2 = g_GG2 + (size_t)n * GLD;
    float r = sigf(G1[c] + G2[c] + bih[c] + bhh[c]);
    float z = sigf(G1[H + c] + G2[H + c] + bih[H + c] + bhh[H + c]);
    float nn = tanhf(G1[2 * H + c] + bih[2 * H + c] + r * (G2[2 * H + c] + bhh[2 * H + c]));
    float hv = (1.0f - z) * nn + z * g_h[n * H + c];
    g_h[n * H + c] = hv;
    g_h16[idx] = __float2half(hv);
}

// ---------------- Set2Set (fused 12 steps, one block per batch) ----------------
#define EVMAX 2048
__global__ __launch_bounds__(256) void k_s2s(const float* __restrict__ Wih,
                                             const float* __restrict__ Whh,
                                             const float* __restrict__ bih,
                                             const float* __restrict__ bhh,
                                             const float* __restrict__ Wout,
                                             const float* __restrict__ bout,
                                             const int* __restrict__ batch,
                                             float* __restrict__ out) {
    extern __shared__ float sm[];
    float* Wa    = sm;
    float* Wb    = Wa + 292 * 73;
    float* bias  = Wb + 292 * 73;
    float* gates = bias + 292;
    float* hh    = gates + 292;
    float* cc    = hh + 73;
    float* rr    = cc + 73;
    float* ev    = rr + 73;
    float* red   = ev + EVMAX;

    int tid = threadIdx.x;
    int b = blockIdx.x;

    for (int i = tid; i < 292 * 73; i += 256) {
        int g = i / 73, k = i % 73;
        Wa[i] = Wih[(size_t)g * 146 + k] + Whh[(size_t)g * 73 + k];
        Wb[i] = Wih[(size_t)g * 146 + 73 + k];
    }
    for (int i = tid; i < 292; i += 256) bias[i] = bih[i] + bhh[i];
    if (tid < H) { hh[tid] = 0.0f; cc[tid] = 0.0f; rr[tid] = 0.0f; }

    int lo = 0, hi = N_NODES;
    while (lo < hi) { int mid = (lo + hi) >> 1; if (batch[mid] < b) lo = mid + 1; else hi = mid; }
    int s0 = lo;
    hi = N_NODES;
    while (lo < hi) { int mid = (lo + hi) >> 1; if (batch[mid] < b + 1) lo = mid + 1; else hi = mid; }
    int len = lo - s0;
    if (len > EVMAX) len = EVMAX;
    __syncthreads();

    int lane = tid & 31, w = tid >> 5;

    for (int t = 0; t < T_S2S; t++) {
        for (int g = tid; g < 292; g += 256) {
            const float* wa = Wa + g * 73;
            const float* wb = Wb + g * 73;
            float acc = bias[g];
            for (int k = 0; k < H; k++) acc += hh[k] * wa[k] + rr[k] * wb[k];
            gates[g] = acc;
        }
        __syncthreads();
        if (tid < H) {
            float ig = gates[tid], fg = gates[H + tid], gg = gates[2 * H + tid], og = gates[3 * H + tid];
            float c2 = sigf(fg) * cc[tid] + sigf(ig) * tanhf(gg);
            cc[tid] = c2;
            hh[tid] = sigf(og) * tanhf(c2);
        }
        __syncthreads();

        if (len > 0) {
            for (int n = w; n < len; n += 8) {
                const float* hrow = g_h + (size_t)(s0 + n) * H;
                float acc = 0.0f;
                for (int c = lane; c < H; c += 32) acc += hrow[c] * hh[c];
#pragma unroll
                for (int o = 16; o; o >>= 1) acc += __shfl_down_sync(0xffffffffu, acc, o);
                if (lane == 0) ev[n] = acc;
            }
            __syncthreads();
            float m = -INFINITY;
            for (int n = tid; n < len; n += 256) m = fmaxf(m, ev[n]);
#pragma unroll
            for (int o = 16; o; o >>= 1) m = fmaxf(m, __shfl_xor_sync(0xffffffffu, m, o));
            if (lane == 0) red[w] = m;
            __syncthreads();
            if (tid == 0) {
                float mm = red[0];
                for (int i = 1; i < 8; i++) mm = fmaxf(mm, red[i]);
                red[32] = mm;
            }
            __syncthreads();
            m = red[32];
            float s = 0.0f;
            for (int n = tid; n < len; n += 256) { float a = expf(ev[n] - m); ev[n] = a; s += a; }
#pragma unroll
            for (int o = 16; o; o >>= 1) s += __shfl_xor_sync(0xffffffffu, s, o);
            if (lane == 0) red[w] = s;
            __syncthreads();
            if (tid == 0) {
                float ss = 0.0f;
                for (int i = 0; i < 8; i++) ss += red[i];
                red[33] = ss;
            }
            __syncthreads();
            float inv = 1.0f / red[33];
            if (tid < H) {
                float acc = 0.0f;
                for (int n = 0; n < len; n++) acc += ev[n] * g_h[(size_t)(s0 + n) * H + tid];
                rr[tid] = acc * inv;
            }
            __syncthreads();
        }
    }

    if (tid == 0) {
        float s = bout[0];
        for (int c = 0; c < H; c++) s += hh[c] * Wout[c];
        out[b] = s;
    }
}

// ---------------- launch ----------------
extern "C" void kernel_launch(void* const* d_in, const int* in_sizes, int n_in,
                              void* d_out, int out_size) {
    const float* nf   = (const float*)d_in[0];
    const float* ef   = (const float*)d_in[1];
    const float* Win  = (const float*)d_in[2];
    const float* bin  = (const float*)d_in[3];
    const float* W1   = (const float*)d_in[4];
    const float* b1   = (const float*)d_in[5];
    const float* W2   = (const float*)d_in[6];
    const float* b2   = (const float*)d_in[7];
    const float* gWih = (const float*)d_in[8];
    const float* gWhh = (const float*)d_in[9];
    const float* gbih = (const float*)d_in[10];
    const float* gbhh = (const float*)d_in[11];
    const float* lWih = (const float*)d_in[12];
    const float* lWhh = (const float*)d_in[13];
    const float* lbih = (const float*)d_in[14];
    const float* lbhh = (const float*)d_in[15];
    const float* Wout = (const float*)d_in[16];
    const float* bout = (const float*)d_in[17];
    const int* Esrc   = (const int*)d_in[18];
    const int* Etgt   = (const int*)d_in[19];
    const int* batch  = (const int*)d_in[20];
    float* out = (float*)d_out;

    __half *p_h16, *p_agg16, *p_W2e, *p_WihT, *p_WhhT;
    float *p_T2, *p_GG1, *p_GG2;
    cudaGetSymbolAddress((void**)&p_h16, g_h16);
    cudaGetSymbolAddress((void**)&p_agg16, g_agg16);
    cudaGetSymbolAddress((void**)&p_W2e, g_W2e);
    cudaGetSymbolAddress((void**)&p_WihT, g_WihT);
    cudaGetSymbolAddress((void**)&p_WhhT, g_WhhT);
    cudaGetSymbolAddress((void**)&p_T2, g_T2);
    cudaGetSymbolAddress((void**)&p_GG1, g_GG1);
    cudaGetSymbolAddress((void**)&p_GG2, g_GG2);

    size_t s2s_smem = (size_t)(2 * 292 * 73 + 292 + 292 + 3 * 73 + EVMAX + 34) * sizeof(float);
    cudaFuncSetAttribute(k_s2s, cudaFuncAttributeMaxDynamicSharedMemorySize, (int)s2s_smem);

    dim3 gT(TWP / 128, N_NODES / 128);   // 43 x 64
    dim3 gG(G3P / 128, N_NODES / 128);   // 2 x 64

    k_prepW2<<<(KP * TWP + 255) / 256, 256>>>(W2, b2);                 // 0
    k_h0<<<(N_NODES * KP + 255) / 256, 256>>>(nf, Win, bin);           // 1
    k_rh<<<(N_EDGES * H + 255) / 256, 256>>>(ef, W1, b1);              // 2
    k_zcnt<<<(N_NODES + 255) / 256, 256>>>();                          // 3
    k_hist<<<(N_EDGES + 255) / 256, 256>>>(Esrc);                      // 4

    k_hgemm<<<gT, 256>>>(p_h16, p_W2e, p_T2, TWP, TW, TW);             // 5: T2 step 0

    k_scan<<<1, 1024>>>();                                              // 6
    k_scatterE<<<(N_EDGES + 255) / 256, 256>>>(Esrc);                  // 7
    k_prepWT<<<(KP * G3P + 255) / 256, 256>>>(gWih, gWhh);             // 8

    for (int t = 0; t < T_MP; t++) {
        if (t > 0)
            k_hgemm<<<gT, 256>>>(p_h16, p_W2e, p_T2, TWP, TW, TW);
        k_zero<<<(N_NODES * H + 255) / 256, 256>>>();
        k_msg2<<<N_NODES, 128>>>(Etgt);
        k_cvt_agg<<<(N_NODES * KP + 255) / 256, 256>>>();
        k_hgemm<<<gG, 256>>>(p_agg16, p_WihT, p_GG1, G3P, GLD, G3);
        k_hgemm<<<gG, 256>>>(p_h16, p_WhhT, p_GG2, G3P, GLD, G3);
        k_grupt<<<(N_NODES * KP + 255) / 256, 256>>>(gbih, gbhh);
    }

    k_s2s<<<NB, 256, s2s_smem>>>(lWih, lWhh, lbih, lbhh, Wout, bout, batch, out);
}

// round 4
// speedup vs baseline: 4.3655x; 1.3602x over previous
#include <cuda_runtime.h>
#include <cuda_fp16.h>
#include <math.h>

#define N_NODES 8192
#define N_EDGES 32768
#define FN 32
#define FE 16
#define H 73
#define HH (H*H)            // 5329
#define KP 80               // padded K for MMA (5 x k16)
#define TW 5402             // T2 logical row width = 73*74
#define TWP 5504            // padded pitch (43*128, 16B-aligned rows in fp16)
#define G3 219
#define G3P 256
#define GLD 220
#define NB 64
#define T_MP 3
#define T_S2S 12

// ---------------- device scratch ----------------
__device__ float g_h[N_NODES * H];
__device__ __half g_h16[N_NODES * KP];
__device__ __half g_agg16[N_NODES * KP];
__device__ float g_RH[N_EDGES * H];
__device__ float g_agg[N_NODES * H];
__device__ __half g_T2[(size_t)N_NODES * TWP];    // 90 MB fp16
__device__ __half g_W2e[KP * TWP];
__device__ __half g_WihT[KP * G3P];
__device__ __half g_WhhT[KP * G3P];
__device__ float g_GG1[N_NODES * GLD];
__device__ float g_GG2[N_NODES * GLD];
__device__ int g_cnt[N_NODES];
__device__ int g_off[N_NODES + 1];
__device__ int g_cur[N_NODES];
__device__ int g_eord[N_EDGES];

__device__ __forceinline__ float sigf(float x) { return 1.0f / (1.0f + expf(-x)); }

__device__ __forceinline__ void ldsm_x4(unsigned &r0, unsigned &r1, unsigned &r2, unsigned &r3, unsigned addr) {
    asm volatile("ldmatrix.sync.aligned.m8n8.x4.shared.b16 {%0,%1,%2,%3},[%4];"
                 : "=r"(r0), "=r"(r1), "=r"(r2), "=r"(r3) : "r"(addr));
}
__device__ __forceinline__ void ldsm_x4t(unsigned &r0, unsigned &r1, unsigned &r2, unsigned &r3, unsigned addr) {
    asm volatile("ldmatrix.sync.aligned.m8n8.x4.trans.shared.b16 {%0,%1,%2,%3},[%4];"
                 : "=r"(r0), "=r"(r1), "=r"(r2), "=r"(r3) : "r"(addr));
}
__device__ __forceinline__ void mma16816(float* d, const unsigned* a, unsigned b0, unsigned b1) {
    asm volatile("mma.sync.aligned.m16n8k16.row.col.f32.f16.f16.f32 "
                 "{%0,%1,%2,%3},{%4,%5,%6,%7},{%8,%9},{%0,%1,%2,%3};"
                 : "+f"(d[0]), "+f"(d[1]), "+f"(d[2]), "+f"(d[3])
                 : "r"(a[0]), "r"(a[1]), "r"(a[2]), "r"(a[3]), "r"(b0), "r"(b1));
}

// ---------------- h0 ----------------
__global__ void k_h0(const float* __restrict__ nf, const float* __restrict__ Win,
                     const float* __restrict__ bin) {
    int idx = blockIdx.x * blockDim.x + threadIdx.x;
    if (idx >= N_NODES * KP) return;
    int n = idx / KP, c = idx % KP;
    if (c >= H) { g_h16[idx] = __float2half(0.0f); return; }
    const float* x = nf + n * FN;
    float acc = bin[c];
#pragma unroll
    for (int k = 0; k < FN; k++) acc += x[k] * Win[k * H + c];
    g_h[n * H + c] = acc;
    g_h16[idx] = __float2half(acc);
}

// ---------------- RH ----------------
__global__ void k_rh(const float* __restrict__ ef, const float* __restrict__ W1,
                     const float* __restrict__ b1) {
    int idx = blockIdx.x * blockDim.x + threadIdx.x;
    if (idx >= N_EDGES * H) return;
    int e = idx / H, c = idx % H;
    const float* x = ef + e * FE;
    float acc = b1[c];
#pragma unroll
    for (int k = 0; k < FE; k++) acc += x[k] * W1[k * H + c];
    g_RH[idx] = fmaxf(acc, 0.0f);
}

// ---------------- prep W2e ----------------
__global__ void k_prepW2(const float* __restrict__ W2, const float* __restrict__ b2) {
    int idx = blockIdx.x * blockDim.x + threadIdx.x;
    if (idx >= KP * TWP) return;
    int j = idx / TWP, c = idx % TWP;
    float v = 0.0f;
    if (j < H && c < TW) {
        int i = c / (H + 1), kk = c % (H + 1);
        v = (kk < H) ? W2[(size_t)kk * HH + i * H + j] : b2[i * H + j];
    }
    g_W2e[idx] = __float2half(v);
}

// ---------------- prep GRU weights ----------------
__global__ void k_prepWT(const float* __restrict__ Wih, const float* __restrict__ Whh) {
    int idx = blockIdx.x * blockDim.x + threadIdx.x;
    if (idx >= KP * G3P) return;
    int k = idx / G3P, g = idx % G3P;
    float a = 0.0f, b = 0.0f;
    if (k < H && g < G3) { a = Wih[(size_t)g * H + k]; b = Whh[(size_t)g * H + k]; }
    g_WihT[idx] = __float2half(a);
    g_WhhT[idx] = __float2half(b);
}

// ---------------- counting sort by src ----------------
__global__ void k_zcnt() {
    int i = blockIdx.x * blockDim.x + threadIdx.x;
    if (i < N_NODES) g_cnt[i] = 0;
}
__global__ void k_hist(const int* __restrict__ Esrc) {
    int e = blockIdx.x * blockDim.x + threadIdx.x;
    if (e < N_EDGES) atomicAdd(&g_cnt[Esrc[e]], 1);
}
__global__ __launch_bounds__(1024) void k_scan() {
    __shared__ int sm_[1024];
    int tid = threadIdx.x;
    int base = tid * 8;
    int v[8], s = 0;
#pragma unroll
    for (int i = 0; i < 8; i++) { v[i] = g_cnt[base + i]; s += v[i]; }
    sm_[tid] = s;
    __syncthreads();
    for (int off = 1; off < 1024; off <<= 1) {
        int t = (tid >= off) ? sm_[tid - off] : 0;
        __syncthreads();
        sm_[tid] += t;
        __syncthreads();
    }
    int run = sm_[tid] - s;
#pragma unroll
    for (int i = 0; i < 8; i++) {
        g_off[base + i] = run;
        g_cur[base + i] = run;
        run += v[i];
    }
    if (tid == 1023) g_off[N_NODES] = run;
}
__global__ void k_scatterE(const int* __restrict__ Esrc) {
    int e = blockIdx.x * blockDim.x + threadIdx.x;
    if (e >= N_EDGES) return;
    int p = atomicAdd(&g_cur[Esrc[e]], 1);
    g_eord[p] = e;
}

// ---------------- fp16 MMA GEMM core: C[M,N] = A[M,80] @ B[80,N] ----------------
// OUT16=1: C is __half, unpredicated half2 stores (pad region writable).
// OUT16=0: C is float, predicated to nreal cols.
template <int OUT16>
__global__ __launch_bounds__(256) void k_hgemm(const __half* __restrict__ A,
                                               const __half* __restrict__ B,
                                               void* __restrict__ Cv,
                                               int ldb, int ldc, int nreal) {
    __shared__ __align__(16) __half As[128][88];
    __shared__ __align__(16) __half Bs[KP][136];
    int tid = threadIdx.x;
    int m0 = blockIdx.y * 128;
    int n0 = blockIdx.x * 128;

    const uint4* Ag = reinterpret_cast<const uint4*>(A + (size_t)m0 * KP);
    for (int idx = tid; idx < 1280; idx += 256) {
        int r = idx / 10, c = idx % 10;
        *reinterpret_cast<uint4*>(&As[r][c * 8]) = Ag[idx];
    }
    for (int idx = tid; idx < 1280; idx += 256) {
        int k = idx >> 4, c = idx & 15;
        *reinterpret_cast<uint4*>(&Bs[k][c * 8]) =
            *reinterpret_cast<const uint4*>(B + (size_t)k * ldb + n0 + c * 8);
    }
    __syncthreads();

    int wid = tid >> 5, lane = tid & 31;
    int wm0 = (wid & 3) * 32;
    int wn0 = (wid >> 2) * 64;

    float acc[2][8][4];
#pragma unroll
    for (int i = 0; i < 2; i++)
#pragma unroll
        for (int j = 0; j < 8; j++)
#pragma unroll
            for (int q = 0; q < 4; q++) acc[i][j][q] = 0.0f;

    unsigned a_base = (unsigned)__cvta_generic_to_shared(&As[0][0]);
    unsigned b_base = (unsigned)__cvta_generic_to_shared(&Bs[0][0]);
    int lr = lane & 15, lc = (lane >> 4) * 8;

#pragma unroll
    for (int ks = 0; ks < 5; ks++) {
        int k0 = ks * 16;
        unsigned af[2][4];
#pragma unroll
        for (int mi = 0; mi < 2; mi++) {
            unsigned addr = a_base + (unsigned)(((wm0 + mi * 16 + lr) * 88 + k0 + lc) * 2);
            ldsm_x4(af[mi][0], af[mi][1], af[mi][2], af[mi][3], addr);
        }
        unsigned bf[4][4];
#pragma unroll
        for (int nj = 0; nj < 4; nj++) {
            unsigned addr = b_base + (unsigned)(((k0 + lr) * 136 + wn0 + nj * 16 + lc) * 2);
            ldsm_x4t(bf[nj][0], bf[nj][1], bf[nj][2], bf[nj][3], addr);
        }
#pragma unroll
        for (int mi = 0; mi < 2; mi++)
#pragma unroll
            for (int nj = 0; nj < 4; nj++) {
                mma16816(acc[mi][2 * nj], af[mi], bf[nj][0], bf[nj][1]);
                mma16816(acc[mi][2 * nj + 1], af[mi], bf[nj][2], bf[nj][3]);
            }
    }

    int gr = lane >> 2, gc = (lane & 3) * 2;
#pragma unroll
    for (int mi = 0; mi < 2; mi++) {
#pragma unroll
        for (int nj8 = 0; nj8 < 8; nj8++) {
            int col = n0 + wn0 + nj8 * 8 + gc;
#pragma unroll
            for (int rr = 0; rr < 2; rr++) {
                int row = m0 + wm0 + mi * 16 + gr + rr * 8;
                float v0 = acc[mi][nj8][rr * 2], v1 = acc[mi][nj8][rr * 2 + 1];
                if (OUT16) {
                    __half* C = (__half*)Cv;
                    *reinterpret_cast<__half2*>(C + (size_t)row * ldc + col) =
                        __floats2half2_rn(v0, v1);
                } else {
                    float* C = (float*)Cv;
                    if (col + 1 < nreal) {
                        *reinterpret_cast<float2*>(C + (size_t)row * ldc + col) =
                            make_float2(v0, v1);
                    } else if (col < nreal) {
                        C[(size_t)row * ldc + col] = v0;
                    }
                }
            }
        }
    }
}

// ---------------- zero agg ----------------
__global__ void k_zero() {
    int i = blockIdx.x * blockDim.x + threadIdx.x;
    if (i < N_NODES * H) g_agg[i] = 0.0f;
}

// ---------------- messages via fp16 T2 ----------------
__global__ __launch_bounds__(96) void k_msg2(const int* __restrict__ Etgt) {
    int src = blockIdx.x;
    int s0 = g_off[src], s1 = g_off[src + 1];
    if (s0 == s1) return;
    __shared__ float rh[8][H];
    __shared__ int tgts[8];
    int tid = threadIdx.x;
    const __half* trow = g_T2 + (size_t)src * TWP;

    for (int base = s0; base < s1; base += 8) {
        int ne = min(8, s1 - base);
        for (int idx = tid; idx < ne * H; idx += 96) {
            int el = idx / H, k = idx - el * H;
            rh[el][k] = g_RH[(size_t)g_eord[base + el] * H + k];
        }
        if (tid < ne) tgts[tid] = Etgt[g_eord[base + tid]];
        __syncthreads();
        if (tid < H) {
            const __half* tp = trow + tid * (H + 1);
            float bterm = __half2float(tp[H]);
            float acc[8];
#pragma unroll
            for (int e = 0; e < 8; e++) acc[e] = bterm;
#pragma unroll 4
            for (int k2 = 0; k2 < 36; k2++) {
                float2 vf = __half22float2(*reinterpret_cast<const __half2*>(tp + 2 * k2));
#pragma unroll
                for (int e = 0; e < 8; e++)
                    if (e < ne) acc[e] += rh[e][2 * k2] * vf.x + rh[e][2 * k2 + 1] * vf.y;
            }
            float v72 = __half2float(tp[72]);
#pragma unroll
            for (int e = 0; e < 8; e++)
                if (e < ne) {
                    acc[e] += rh[e][72] * v72;
                    atomicAdd(&g_agg[(size_t)tgts[e] * H + tid], acc[e]);
                }
        }
        __syncthreads();
    }
}

// ---------------- convert agg to fp16 padded ----------------
__global__ void k_cvt_agg() {
    int idx = blockIdx.x * blockDim.x + threadIdx.x;
    if (idx >= N_NODES * KP) return;
    int n = idx / KP, c = idx % KP;
    g_agg16[idx] = __float2half((c < H) ? g_agg[n * H + c] : 0.0f);
}

// ---------------- GRU pointwise ----------------
__global__ void k_grupt(const float* __restrict__ bih, const float* __restrict__ bhh) {
    int idx = blockIdx.x * blockDim.x + threadIdx.x;
    if (idx >= N_NODES * KP) return;
    int n = idx / KP, c = idx % KP;
    if (c >= H) { g_h16[idx] = __float2half(0.0f); return; }
    const float* G1 = g_GG1 + (size_t)n * GLD;
    const float* G2 = g_GG2 + (size_t)n * GLD;
    float r = sigf(G1[c] + G2[c] + bih[c] + bhh[c]);
    float z = sigf(G1[H + c] + G2[H + c] + bih[H + c] + bhh[H + c]);
    float nn = tanhf(G1[2 * H + c] + bih[2 * H + c] + r * (G2[2 * H + c] + bhh[2 * H + c]));
    float hv = (1.0f - z) * nn + z * g_h[n * H + c];
    g_h[n * H + c] = hv;
    g_h16[idx] = __float2half(hv);
}

// ---------------- Set2Set ----------------
#define EVMAX 2048
__global__ __launch_bounds__(256) void k_s2s(const float* __restrict__ Wih,
                                             const float* __restrict__ Whh,
                                             const float* __restrict__ bih,
                                             const float* __restrict__ bhh,
                                             const float* __restrict__ Wout,
                                             const float* __restrict__ bout,
                                             const int* __restrict__ batch,
                                             float* __restrict__ out) {
    extern __shared__ float sm[];
    float* Wa    = sm;
    float* Wb    = Wa + 292 * 73;
    float* bias  = Wb + 292 * 73;
    float* gates = bias + 292;
    float* hh    = gates + 292;
    float* cc    = hh + 73;
    float* rr    = cc + 73;
    float* ev    = rr + 73;
    float* red   = ev + EVMAX;

    int tid = threadIdx.x;
    int b = blockIdx.x;

    for (int i = tid; i < 292 * 73; i += 256) {
        int g = i / 73, k = i % 73;
        Wa[i] = Wih[(size_t)g * 146 + k] + Whh[(size_t)g * 73 + k];
        Wb[i] = Wih[(size_t)g * 146 + 73 + k];
    }
    for (int i = tid; i < 292; i += 256) bias[i] = bih[i] + bhh[i];
    if (tid < H) { hh[tid] = 0.0f; cc[tid] = 0.0f; rr[tid] = 0.0f; }

    int lo = 0, hi = N_NODES;
    while (lo < hi) { int mid = (lo + hi) >> 1; if (batch[mid] < b) lo = mid + 1; else hi = mid; }
    int s0 = lo;
    hi = N_NODES;
    while (lo < hi) { int mid = (lo + hi) >> 1; if (batch[mid] < b + 1) lo = mid + 1; else hi = mid; }
    int len = lo - s0;
    if (len > EVMAX) len = EVMAX;
    __syncthreads();

    int lane = tid & 31, w = tid >> 5;

    for (int t = 0; t < T_S2S; t++) {
        for (int g = tid; g < 292; g += 256) {
            const float* wa = Wa + g * 73;
            const float* wb = Wb + g * 73;
            float acc = bias[g];
            for (int k = 0; k < H; k++) acc += hh[k] * wa[k] + rr[k] * wb[k];
            gates[g] = acc;
        }
        __syncthreads();
        if (tid < H) {
            float ig = gates[tid], fg = gates[H + tid], gg = gates[2 * H + tid], og = gates[3 * H + tid];
            float c2 = sigf(fg) * cc[tid] + sigf(ig) * tanhf(gg);
            cc[tid] = c2;
            hh[tid] = sigf(og) * tanhf(c2);
        }
        __syncthreads();

        if (len > 0) {
            for (int n = w; n < len; n += 8) {
                const float* hrow = g_h + (size_t)(s0 + n) * H;
                float acc = 0.0f;
                for (int c = lane; c < H; c += 32) acc += hrow[c] * hh[c];
#pragma unroll
                for (int o = 16; o; o >>= 1) acc += __shfl_down_sync(0xffffffffu, acc, o);
                if (lane == 0) ev[n] = acc;
            }
            __syncthreads();
            float m = -INFINITY;
            for (int n = tid; n < len; n += 256) m = fmaxf(m, ev[n]);
#pragma unroll
            for (int o = 16; o; o >>= 1) m = fmaxf(m, __shfl_xor_sync(0xffffffffu, m, o));
            if (lane == 0) red[w] = m;
            __syncthreads();
            if (tid == 0) {
                float mm = red[0];
                for (int i = 1; i < 8; i++) mm = fmaxf(mm, red[i]);
                red[32] = mm;
            }
            __syncthreads();
            m = red[32];
            float s = 0.0f;
            for (int n = tid; n < len; n += 256) { float a = expf(ev[n] - m); ev[n] = a; s += a; }
#pragma unroll
            for (int o = 16; o; o >>= 1) s += __shfl_xor_sync(0xffffffffu, s, o);
            if (lane == 0) red[w] = s;
            __syncthreads();
            if (tid == 0) {
                float ss = 0.0f;
                for (int i = 0; i < 8; i++) ss += red[i];
                red[33] = ss;
            }
            __syncthreads();
            float inv = 1.0f / red[33];
            if (tid < H) {
                float acc = 0.0f;
                for (int n = 0; n < len; n++) acc += ev[n] * g_h[(size_t)(s0 + n) * H + tid];
                rr[tid] = acc * inv;
            }
            __syncthreads();
        }
    }

    if (tid == 0) {
        float s = bout[0];
        for (int c = 0; c < H; c++) s += hh[c] * Wout[c];
        out[b] = s;
    }
}

// ---------------- launch ----------------
extern "C" void kernel_launch(void* const* d_in, const int* in_sizes, int n_in,
                              void* d_out, int out_size) {
    const float* nf   = (const float*)d_in[0];
    const float* ef   = (const float*)d_in[1];
    const float* Win  = (const float*)d_in[2];
    const float* bin  = (const float*)d_in[3];
    const float* W1   = (const float*)d_in[4];
    const float* b1   = (const float*)d_in[5];
    const float* W2   = (const float*)d_in[6];
    const float* b2   = (const float*)d_in[7];
    const float* gWih = (const float*)d_in[8];
    const float* gWhh = (const float*)d_in[9];
    const float* gbih = (const float*)d_in[10];
    const float* gbhh = (const float*)d_in[11];
    const float* lWih = (const float*)d_in[12];
    const float* lWhh = (const float*)d_in[13];
    const float* lbih = (const float*)d_in[14];
    const float* lbhh = (const float*)d_in[15];
    const float* Wout = (const float*)d_in[16];
    const float* bout = (const float*)d_in[17];
    const int* Esrc   = (const int*)d_in[18];
    const int* Etgt   = (const int*)d_in[19];
    const int* batch  = (const int*)d_in[20];
    float* out = (float*)d_out;

    __half *p_h16, *p_agg16, *p_W2e, *p_WihT, *p_WhhT, *p_T2;
    float *p_GG1, *p_GG2;
    cudaGetSymbolAddress((void**)&p_h16, g_h16);
    cudaGetSymbolAddress((void**)&p_agg16, g_agg16);
    cudaGetSymbolAddress((void**)&p_W2e, g_W2e);
    cudaGetSymbolAddress((void**)&p_WihT, g_WihT);
    cudaGetSymbolAddress((void**)&p_WhhT, g_WhhT);
    cudaGetSymbolAddress((void**)&p_T2, g_T2);
    cudaGetSymbolAddress((void**)&p_GG1, g_GG1);
    cudaGetSymbolAddress((void**)&p_GG2, g_GG2);

    size_t s2s_smem = (size_t)(2 * 292 * 73 + 292 + 292 + 3 * 73 + EVMAX + 34) * sizeof(float);
    cudaFuncSetAttribute(k_s2s, cudaFuncAttributeMaxDynamicSharedMemorySize, (int)s2s_smem);

    dim3 gT(TWP / 128, N_NODES / 128);   // 43 x 64
    dim3 gG(G3P / 128, N_NODES / 128);   // 2 x 64

    k_prepW2<<<(KP * TWP + 255) / 256, 256>>>(W2, b2);
    k_h0<<<(N_NODES * KP + 255) / 256, 256>>>(nf, Win, bin);
    k_rh<<<(N_EDGES * H + 255) / 256, 256>>>(ef, W1, b1);
    k_zcnt<<<(N_NODES + 255) / 256, 256>>>();
    k_hist<<<(N_EDGES + 255) / 256, 256>>>(Esrc);

    k_hgemm<1><<<gT, 256>>>(p_h16, p_W2e, p_T2, TWP, TWP, TWP);

    k_scan<<<1, 1024>>>();
    k_scatterE<<<(N_EDGES + 255) / 256, 256>>>(Esrc);
    k_prepWT<<<(KP * G3P + 255) / 256, 256>>>(gWih, gWhh);

    for (int t = 0; t < T_MP; t++) {
        if (t > 0)
            k_hgemm<1><<<gT, 256>>>(p_h16, p_W2e, p_T2, TWP, TWP, TWP);
        k_zero<<<(N_NODES * H + 255) / 256, 256>>>();
        k_msg2<<<N_NODES, 96>>>(Etgt);
        k_cvt_agg<<<(N_NODES * KP + 255) / 256, 256>>>();
        k_hgemm<0><<<gG, 256>>>(p_agg16, p_WihT, p_GG1, G3P, GLD, G3);
        k_hgemm<0><<<gG, 256>>>(p_h16, p_WhhT, p_GG2, G3P, GLD, G3);
        k_grupt<<<(N_NODES * KP + 255) / 256, 256>>>(gbih, gbhh);
    }

    k_s2s<<<NB, 256, s2s_smem>>>(lWih, lWhh, lbih, lbhh, Wout, bout, batch, out);
}